// round 8
// baseline (speedup 1.0000x reference)
#include <cuda_runtime.h>
#include <cuda_bf16.h>
#include <cstdint>
#include <cstddef>

#define NNODES 100000
#define NEDGES 500000
#define FEAT   128
#define WPSZ   16384   // uint32 per layer fragment buffer (64KB)

// ---------------- scratch (device globals; no allocations allowed) ----------
__device__ int      g_cnt[NNODES];
__device__ int      g_rowoff[NNODES + 1];
__device__ int      g_cursor[NNODES];
__device__ float    g_dinv[NNODES];
__device__ int      g_esrc[NEDGES];
__device__ float    g_bufA[(size_t)NNODES * FEAT];
__device__ float    g_bufB[(size_t)NNODES * FEAT];
__device__ float    g_bufY[(size_t)NNODES * FEAT];
__device__ uint32_t g_Wp[4 * WPSZ];   // permuted tf32 W fragments, 4 x 64KB
__device__ int      g_bsum[128];
__device__ int      g_boff[128];

// ---------------- CSR build --------------------------------------------------
__global__ void k_init_cnt() {
    int i = blockIdx.x * blockDim.x + threadIdx.x;
    if (i < NNODES) g_cnt[i] = 0;
}

__global__ void k_count(const int* __restrict__ dst) {
    int e = blockIdx.x * blockDim.x + threadIdx.x;
    if (e < NEDGES) atomicAdd(&g_cnt[dst[e]], 1);
}

__global__ void k_scan1() {
    __shared__ int sh[256];
    int t = threadIdx.x;
    int base = blockIdx.x * 1024;
    int v[4];
    int s = 0;
#pragma unroll
    for (int j = 0; j < 4; j++) {
        int idx = base + t * 4 + j;
        v[j] = (idx < NNODES) ? g_cnt[idx] : 0;
        s += v[j];
    }
    sh[t] = s;
    __syncthreads();
    for (int off = 1; off < 256; off <<= 1) {
        int x = (t >= off) ? sh[t - off] : 0;
        __syncthreads();
        sh[t] += x;
        __syncthreads();
    }
    int excl = sh[t] - s;
    if (t == 255) g_bsum[blockIdx.x] = sh[255];
    int run = excl;
#pragma unroll
    for (int j = 0; j < 4; j++) {
        int idx = base + t * 4 + j;
        if (idx < NNODES) g_rowoff[idx] = run;
        run += v[j];
    }
}

__global__ void k_scan2(int nb) {
    __shared__ int sh[128];
    int t = threadIdx.x;
    int v = (t < nb) ? g_bsum[t] : 0;
    sh[t] = v;
    __syncthreads();
    for (int off = 1; off < 128; off <<= 1) {
        int x = (t >= off) ? sh[t - off] : 0;
        __syncthreads();
        sh[t] += x;
        __syncthreads();
    }
    g_boff[t] = sh[t] - v;
}

__global__ void k_finalize() {
    int i = blockIdx.x * blockDim.x + threadIdx.x;
    if (i < NNODES) {
        int r = g_rowoff[i] + g_boff[i >> 10];
        g_rowoff[i] = r;
        g_cursor[i] = r;
        g_dinv[i] = rsqrtf((float)(g_cnt[i] + 1));
    }
    if (i == 0) g_rowoff[NNODES] = NEDGES;
}

__global__ void k_fill(const int* __restrict__ src, const int* __restrict__ dst) {
    int e = blockIdx.x * blockDim.x + threadIdx.x;
    if (e < NEDGES) {
        int p = atomicAdd(&g_cursor[dst[e]], 1);
        g_esrc[p] = src[e];
    }
}

// ---------------- W permute (all 4 layers at once) ---------------------------
__device__ __forceinline__ uint32_t f2tf32(float v) {
    uint32_t r;
    asm("cvt.rna.tf32.f32 %0, %1;" : "=r"(r) : "f"(v));
    return r;
}

__global__ void k_prepW_all(const float* __restrict__ W0, const float* __restrict__ W1,
                            const float* __restrict__ W2, const float* __restrict__ W3) {
    int gidx = blockIdx.x * blockDim.x + threadIdx.x;  // 0..65535
    int layer = gidx >> 14;
    int idx = gidx & (WPSZ - 1);
    const float* W = (layer == 0) ? W0 : (layer == 1) ? W1 : (layer == 2) ? W2 : W3;
    int Mout = (layer == 3) ? 40 : 128;
    int k = idx >> 7, c = idx & 127;
    float v = (c < Mout) ? W[k * Mout + c] : 0.f;
    int ntile = c >> 3, gid = c & 7;
    int kstep = k >> 3, klow = k & 7, slot = klow >> 2, tig = klow & 3;
    g_Wp[layer * WPSZ + ((ntile * 16 + kstep) * 32 + gid * 4 + tig) * 2 + slot] = f2tf32(v);
}

// ---------------- tensor-core GEMM ------------------------------------------
// Y[i][c] = sum_k X[i][k] * W[k][c]   (NO dinv scaling here — moved to agg)
__global__ __launch_bounds__(256, 2) void k_gemm_tc(const float* __restrict__ X,
                                                    float* __restrict__ Y, int Mout,
                                                    const uint32_t* __restrict__ Wp) {
    extern __shared__ float smem[];
    float* As = smem;  // [8 mtile][16 kstep][32 lane][4] = 16384 floats = 64KB

    int t = threadIdx.x;
    int row0 = blockIdx.x * 128;

    // X tile -> As (permuted, tf32, zero-fill OOB rows)
    for (int idx = t; idx < 128 * 32; idx += 256) {
        int r = idx >> 5;
        int kc = (idx & 31) * 4;
        int grow = row0 + r;
        float4 v = (grow < NNODES)
                       ? *(const float4*)(X + (size_t)grow * 128 + kc)
                       : make_float4(0.f, 0.f, 0.f, 0.f);
        float vv[4] = {v.x, v.y, v.z, v.w};
        int mtile = r >> 4, rlow = r & 15;
        int half = rlow >> 3, gid = rlow & 7;
#pragma unroll
        for (int j = 0; j < 4; j++) {
            int k = kc + j;
            int kstep = k >> 3, klow = k & 7, khalf = klow >> 2, tig = klow & 3;
            As[((mtile * 16 + kstep) * 32 + gid * 4 + tig) * 4 + half + 2 * khalf] =
                __uint_as_float(f2tf32(vv[j]));
        }
    }
    __syncthreads();

    int warp = t >> 5, lane = t & 31;
    int wm = warp >> 1, wn = warp & 1;  // 4 x 2 warp grid

    float acc[2][8][4];
#pragma unroll
    for (int im = 0; im < 2; im++)
#pragma unroll
        for (int in = 0; in < 8; in++)
#pragma unroll
            for (int j = 0; j < 4; j++) acc[im][in][j] = 0.f;

#pragma unroll 4
    for (int ks = 0; ks < 16; ks++) {
        uint4 a[2];
#pragma unroll
        for (int im = 0; im < 2; im++)
            a[im] = *(const uint4*)&As[(((wm * 2 + im) * 16 + ks) * 32 + lane) * 4];
        uint2 b[8];
#pragma unroll
        for (int in = 0; in < 8; in++)
            b[in] = __ldg((const uint2*)&Wp[(((wn * 8 + in) * 16 + ks) * 32 + lane) * 2]);
#pragma unroll
        for (int im = 0; im < 2; im++)
#pragma unroll
            for (int in = 0; in < 8; in++)
                asm volatile(
                    "mma.sync.aligned.m16n8k8.row.col.f32.tf32.tf32.f32 "
                    "{%0,%1,%2,%3}, {%4,%5,%6,%7}, {%8,%9}, {%0,%1,%2,%3};"
                    : "+f"(acc[im][in][0]), "+f"(acc[im][in][1]),
                      "+f"(acc[im][in][2]), "+f"(acc[im][in][3])
                    : "r"(a[im].x), "r"(a[im].y), "r"(a[im].z), "r"(a[im].w),
                      "r"(b[in].x), "r"(b[in].y));
    }

    // epilogue (no dinv)
    int gid = lane >> 2, tig = lane & 3;
#pragma unroll
    for (int im = 0; im < 2; im++) {
        int r_lo = row0 + wm * 32 + im * 16 + gid;
        int r_hi = r_lo + 8;
#pragma unroll
        for (int in = 0; in < 8; in++) {
            int c = wn * 64 + in * 8 + tig * 2;
            if (Mout == 128) {
                if (r_lo < NNODES)
                    *(float2*)(Y + (size_t)r_lo * 128 + c) =
                        make_float2(acc[im][in][0], acc[im][in][1]);
                if (r_hi < NNODES)
                    *(float2*)(Y + (size_t)r_hi * 128 + c) =
                        make_float2(acc[im][in][2], acc[im][in][3]);
            } else {
                if (r_lo < NNODES) {
                    if (c < Mout)     Y[(size_t)r_lo * Mout + c]     = acc[im][in][0];
                    if (c + 1 < Mout) Y[(size_t)r_lo * Mout + c + 1] = acc[im][in][1];
                }
                if (r_hi < NNODES) {
                    if (c < Mout)     Y[(size_t)r_hi * Mout + c]     = acc[im][in][2];
                    if (c + 1 < Mout) Y[(size_t)r_hi * Mout + c + 1] = acc[im][in][3];
                }
            }
        }
    }
}

// ---------------- aggregation: warp per node, 4-way pipelined gather ---------
// out[i] = relu?( dinv_i*(sum_e dinv_src*Y[src] + dinv_i*Y[i]) + bias )
__global__ void k_agg(const float* __restrict__ Y, const float* __restrict__ bias,
                      float* __restrict__ Hout, int Mout, int dorelu) {
    int warp = (blockIdx.x * blockDim.x + threadIdx.x) >> 5;
    int lane = threadIdx.x & 31;
    if (warp >= NNODES) return;
    int f = lane * 4;
    if (f >= Mout) return;

    int beg = g_rowoff[warp];
    int end = g_rowoff[warp + 1];
    float dv = g_dinv[warp];

    // self loop: dinv_i * Y[i]
    float4 vself = *(const float4*)(Y + (size_t)warp * Mout + f);
    float4 s0 = make_float4(dv * vself.x, dv * vself.y, dv * vself.z, dv * vself.w);
    float4 s1 = make_float4(0.f, 0.f, 0.f, 0.f);

    int j = beg;
    for (; j + 4 <= end; j += 4) {
        int i0 = __ldg(&g_esrc[j]);
        int i1 = __ldg(&g_esrc[j + 1]);
        int i2 = __ldg(&g_esrc[j + 2]);
        int i3 = __ldg(&g_esrc[j + 3]);
        float d0 = __ldg(&g_dinv[i0]);
        float d1 = __ldg(&g_dinv[i1]);
        float d2 = __ldg(&g_dinv[i2]);
        float d3 = __ldg(&g_dinv[i3]);
        float4 v0 = __ldg((const float4*)(Y + (size_t)i0 * Mout + f));
        float4 v1 = __ldg((const float4*)(Y + (size_t)i1 * Mout + f));
        float4 v2 = __ldg((const float4*)(Y + (size_t)i2 * Mout + f));
        float4 v3 = __ldg((const float4*)(Y + (size_t)i3 * Mout + f));
        s0.x = fmaf(d0, v0.x, s0.x); s0.y = fmaf(d0, v0.y, s0.y);
        s0.z = fmaf(d0, v0.z, s0.z); s0.w = fmaf(d0, v0.w, s0.w);
        s1.x = fmaf(d1, v1.x, s1.x); s1.y = fmaf(d1, v1.y, s1.y);
        s1.z = fmaf(d1, v1.z, s1.z); s1.w = fmaf(d1, v1.w, s1.w);
        s0.x = fmaf(d2, v2.x, s0.x); s0.y = fmaf(d2, v2.y, s0.y);
        s0.z = fmaf(d2, v2.z, s0.z); s0.w = fmaf(d2, v2.w, s0.w);
        s1.x = fmaf(d3, v3.x, s1.x); s1.y = fmaf(d3, v3.y, s1.y);
        s1.z = fmaf(d3, v3.z, s1.z); s1.w = fmaf(d3, v3.w, s1.w);
    }
    for (; j < end; j++) {
        int si = __ldg(&g_esrc[j]);
        float ds = __ldg(&g_dinv[si]);
        float4 v = __ldg((const float4*)(Y + (size_t)si * Mout + f));
        s0.x = fmaf(ds, v.x, s0.x); s0.y = fmaf(ds, v.y, s0.y);
        s0.z = fmaf(ds, v.z, s0.z); s0.w = fmaf(ds, v.w, s0.w);
    }
    float4 s = make_float4(s0.x + s1.x, s0.y + s1.y, s0.z + s1.z, s0.w + s1.w);

    float4 bb = *(const float4*)(bias + f);
    float4 o = make_float4(fmaf(dv, s.x, bb.x), fmaf(dv, s.y, bb.y),
                           fmaf(dv, s.z, bb.z), fmaf(dv, s.w, bb.w));
    if (dorelu) {
        o.x = fmaxf(o.x, 0.f); o.y = fmaxf(o.y, 0.f);
        o.z = fmaxf(o.z, 0.f); o.w = fmaxf(o.w, 0.f);
    }
    *(float4*)(Hout + (size_t)warp * Mout + f) = o;
}

// ---------------- launch -----------------------------------------------------
extern "C" void kernel_launch(void* const* d_in, const int* in_sizes, int n_in,
                              void* d_out, int out_size) {
    const float* x = (const float*)d_in[0];
    const int* ei = (const int*)d_in[1];
    const int* src = ei;
    const int* dst = ei + NEDGES;
    const float* W0 = (const float*)d_in[2];
    const float* b0 = (const float*)d_in[3];
    const float* W1 = (const float*)d_in[4];
    const float* b1 = (const float*)d_in[5];
    const float* W2 = (const float*)d_in[6];
    const float* b2 = (const float*)d_in[7];
    const float* W3 = (const float*)d_in[8];
    const float* b3 = (const float*)d_in[9];
    float* out = (float*)d_out;

    float *bufA, *bufB, *bufY;
    uint32_t* Wp;
    cudaGetSymbolAddress((void**)&bufA, g_bufA);
    cudaGetSymbolAddress((void**)&bufB, g_bufB);
    cudaGetSymbolAddress((void**)&bufY, g_bufY);
    cudaGetSymbolAddress((void**)&Wp, g_Wp);

    const int NT = 256;
    int gN = (NNODES + NT - 1) / NT;
    int gE = (NEDGES + NT - 1) / NT;
    int gScan = (NNODES + 1023) / 1024;

    size_t shmem = 16384 * sizeof(float);  // 64KB (As only)
    static int smem_set = 0;
    if (!smem_set) {
        cudaFuncSetAttribute(k_gemm_tc, cudaFuncAttributeMaxDynamicSharedMemorySize,
                             (int)shmem);
        smem_set = 1;
    }

    // side stream + events, created once on the first (uncaptured) call
    static cudaStream_t s_side = nullptr;
    static cudaEvent_t ev_fork = nullptr, ev_join = nullptr;
    if (s_side == nullptr) {
        cudaStreamCreateWithFlags(&s_side, cudaStreamNonBlocking);
        cudaEventCreateWithFlags(&ev_fork, cudaEventDisableTiming);
        cudaEventCreateWithFlags(&ev_join, cudaEventDisableTiming);
    }

    int gGemm = (NNODES + 127) / 128;          // 782
    int gAgg = (NNODES * 32 + NT - 1) / NT;    // 12500

    // fork: CSR build on side stream, overlapped with prepW + layer-0 GEMM
    cudaEventRecord(ev_fork, 0);
    cudaStreamWaitEvent(s_side, ev_fork, 0);
    k_init_cnt<<<gN, NT, 0, s_side>>>();
    k_count<<<gE, NT, 0, s_side>>>(dst);
    k_scan1<<<gScan, NT, 0, s_side>>>();
    k_scan2<<<1, 128, 0, s_side>>>(gScan);
    k_finalize<<<gN, NT, 0, s_side>>>();
    k_fill<<<gE, NT, 0, s_side>>>(src, dst);
    cudaEventRecord(ev_join, s_side);

    // main stream: weight prep + layer-0 GEMM (independent of CSR)
    k_prepW_all<<<256, 256>>>(W0, W1, W2, W3);
    k_gemm_tc<<<gGemm, NT, shmem>>>(x, bufY, 128, Wp);

    // join: aggregation needs CSR + dinv
    cudaStreamWaitEvent(0, ev_join, 0);
    k_agg<<<gAgg, NT>>>(bufY, b0, bufA, 128, 1);
    // layer 1
    k_gemm_tc<<<gGemm, NT, shmem>>>(bufA, bufY, 128, Wp + WPSZ);
    k_agg<<<gAgg, NT>>>(bufY, b1, bufB, 128, 1);
    // layer 2
    k_gemm_tc<<<gGemm, NT, shmem>>>(bufB, bufY, 128, Wp + 2 * WPSZ);
    k_agg<<<gAgg, NT>>>(bufY, b2, bufA, 128, 1);
    // layer 3 (C = 40, no relu)
    k_gemm_tc<<<gGemm, NT, shmem>>>(bufA, bufY, 40, Wp + 3 * WPSZ);
    k_agg<<<gAgg, NT>>>(bufY, b3, out, 40, 0);
}

// round 9
// speedup vs baseline: 1.0013x; 1.0013x over previous
#include <cuda_runtime.h>
#include <cuda_bf16.h>
#include <cstdint>
#include <cstddef>

#define NNODES 100000
#define NEDGES 500000
#define FEAT   128
#define WPSZ   16384   // uint32 per layer fragment buffer (64KB)

// ---------------- scratch (device globals; no allocations allowed) ----------
__device__ int      g_cnt[NNODES];
__device__ int      g_rowoff[NNODES + 1];
__device__ int      g_cursor[NNODES];
__device__ float    g_dinv[NNODES];
__device__ int      g_esrc[NEDGES];
__device__ float    g_bufA[(size_t)NNODES * FEAT];
__device__ float    g_bufB[(size_t)NNODES * FEAT];
__device__ float    g_bufY[(size_t)NNODES * FEAT];
__device__ uint32_t g_Wp[4 * WPSZ];   // permuted tf32 W fragments, 4 x 64KB
__device__ int      g_bsum[128];
__device__ int      g_boff[128];

// ---------------- CSR build --------------------------------------------------
__global__ void k_init_cnt() {
    int i = blockIdx.x * blockDim.x + threadIdx.x;
    if (i < NNODES) g_cnt[i] = 0;
}

__global__ void k_count(const int* __restrict__ dst) {
    int e = blockIdx.x * blockDim.x + threadIdx.x;
    if (e < NEDGES) atomicAdd(&g_cnt[dst[e]], 1);
}

__global__ void k_scan1() {
    __shared__ int sh[256];
    int t = threadIdx.x;
    int base = blockIdx.x * 1024;
    int v[4];
    int s = 0;
#pragma unroll
    for (int j = 0; j < 4; j++) {
        int idx = base + t * 4 + j;
        v[j] = (idx < NNODES) ? g_cnt[idx] : 0;
        s += v[j];
    }
    sh[t] = s;
    __syncthreads();
    for (int off = 1; off < 256; off <<= 1) {
        int x = (t >= off) ? sh[t - off] : 0;
        __syncthreads();
        sh[t] += x;
        __syncthreads();
    }
    int excl = sh[t] - s;
    if (t == 255) g_bsum[blockIdx.x] = sh[255];
    int run = excl;
#pragma unroll
    for (int j = 0; j < 4; j++) {
        int idx = base + t * 4 + j;
        if (idx < NNODES) g_rowoff[idx] = run;
        run += v[j];
    }
}

__global__ void k_scan2(int nb) {
    __shared__ int sh[128];
    int t = threadIdx.x;
    int v = (t < nb) ? g_bsum[t] : 0;
    sh[t] = v;
    __syncthreads();
    for (int off = 1; off < 128; off <<= 1) {
        int x = (t >= off) ? sh[t - off] : 0;
        __syncthreads();
        sh[t] += x;
        __syncthreads();
    }
    g_boff[t] = sh[t] - v;
}

__global__ void k_finalize() {
    int i = blockIdx.x * blockDim.x + threadIdx.x;
    if (i < NNODES) {
        int r = g_rowoff[i] + g_boff[i >> 10];
        g_rowoff[i] = r;
        g_cursor[i] = r;
        g_dinv[i] = rsqrtf((float)(g_cnt[i] + 1));
    }
    if (i == 0) g_rowoff[NNODES] = NEDGES;
}

__global__ void k_fill(const int* __restrict__ src, const int* __restrict__ dst) {
    int e = blockIdx.x * blockDim.x + threadIdx.x;
    if (e < NEDGES) {
        int p = atomicAdd(&g_cursor[dst[e]], 1);
        g_esrc[p] = src[e];
    }
}

// ---------------- W permute (all 4 layers at once) ---------------------------
__device__ __forceinline__ uint32_t f2tf32(float v) {
    uint32_t r;
    asm("cvt.rna.tf32.f32 %0, %1;" : "=r"(r) : "f"(v));
    return r;
}

__global__ void k_prepW_all(const float* __restrict__ W0, const float* __restrict__ W1,
                            const float* __restrict__ W2, const float* __restrict__ W3) {
    int gidx = blockIdx.x * blockDim.x + threadIdx.x;  // 0..65535
    int layer = gidx >> 14;
    int idx = gidx & (WPSZ - 1);
    const float* W = (layer == 0) ? W0 : (layer == 1) ? W1 : (layer == 2) ? W2 : W3;
    int Mout = (layer == 3) ? 40 : 128;
    int k = idx >> 7, c = idx & 127;
    float v = (c < Mout) ? W[k * Mout + c] : 0.f;
    int ntile = c >> 3, gid = c & 7;
    int kstep = k >> 3, klow = k & 7, slot = klow >> 2, tig = klow & 3;
    g_Wp[layer * WPSZ + ((ntile * 16 + kstep) * 32 + gid * 4 + tig) * 2 + slot] = f2tf32(v);
}

// ---------------- tensor-core GEMM ------------------------------------------
// Y[i][c] = sum_k X[i][k] * W[k][c]   (NO dinv scaling here — moved to agg)
__global__ __launch_bounds__(256, 2) void k_gemm_tc(const float* __restrict__ X,
                                                    float* __restrict__ Y, int Mout,
                                                    const uint32_t* __restrict__ Wp) {
    extern __shared__ float smem[];
    float* As = smem;  // [8 mtile][16 kstep][32 lane][4] = 16384 floats = 64KB

    int t = threadIdx.x;
    int row0 = blockIdx.x * 128;

    // X tile -> As (permuted, tf32, zero-fill OOB rows)
    for (int idx = t; idx < 128 * 32; idx += 256) {
        int r = idx >> 5;
        int kc = (idx & 31) * 4;
        int grow = row0 + r;
        float4 v = (grow < NNODES)
                       ? *(const float4*)(X + (size_t)grow * 128 + kc)
                       : make_float4(0.f, 0.f, 0.f, 0.f);
        float vv[4] = {v.x, v.y, v.z, v.w};
        int mtile = r >> 4, rlow = r & 15;
        int half = rlow >> 3, gid = rlow & 7;
#pragma unroll
        for (int j = 0; j < 4; j++) {
            int k = kc + j;
            int kstep = k >> 3, klow = k & 7, khalf = klow >> 2, tig = klow & 3;
            As[((mtile * 16 + kstep) * 32 + gid * 4 + tig) * 4 + half + 2 * khalf] =
                __uint_as_float(f2tf32(vv[j]));
        }
    }
    __syncthreads();

    int warp = t >> 5, lane = t & 31;
    int wm = warp >> 1, wn = warp & 1;  // 4 x 2 warp grid

    float acc[2][8][4];
#pragma unroll
    for (int im = 0; im < 2; im++)
#pragma unroll
        for (int in = 0; in < 8; in++)
#pragma unroll
            for (int j = 0; j < 4; j++) acc[im][in][j] = 0.f;

#pragma unroll 4
    for (int ks = 0; ks < 16; ks++) {
        uint4 a[2];
#pragma unroll
        for (int im = 0; im < 2; im++)
            a[im] = *(const uint4*)&As[(((wm * 2 + im) * 16 + ks) * 32 + lane) * 4];
        uint2 b[8];
#pragma unroll
        for (int in = 0; in < 8; in++)
            b[in] = __ldg((const uint2*)&Wp[(((wn * 8 + in) * 16 + ks) * 32 + lane) * 2]);
#pragma unroll
        for (int im = 0; im < 2; im++)
#pragma unroll
            for (int in = 0; in < 8; in++)
                asm volatile(
                    "mma.sync.aligned.m16n8k8.row.col.f32.tf32.tf32.f32 "
                    "{%0,%1,%2,%3}, {%4,%5,%6,%7}, {%8,%9}, {%0,%1,%2,%3};"
                    : "+f"(acc[im][in][0]), "+f"(acc[im][in][1]),
                      "+f"(acc[im][in][2]), "+f"(acc[im][in][3])
                    : "r"(a[im].x), "r"(a[im].y), "r"(a[im].z), "r"(a[im].w),
                      "r"(b[in].x), "r"(b[in].y));
    }

    // epilogue (no dinv)
    int gid = lane >> 2, tig = lane & 3;
#pragma unroll
    for (int im = 0; im < 2; im++) {
        int r_lo = row0 + wm * 32 + im * 16 + gid;
        int r_hi = r_lo + 8;
#pragma unroll
        for (int in = 0; in < 8; in++) {
            int c = wn * 64 + in * 8 + tig * 2;
            if (Mout == 128) {
                if (r_lo < NNODES)
                    *(float2*)(Y + (size_t)r_lo * 128 + c) =
                        make_float2(acc[im][in][0], acc[im][in][1]);
                if (r_hi < NNODES)
                    *(float2*)(Y + (size_t)r_hi * 128 + c) =
                        make_float2(acc[im][in][2], acc[im][in][3]);
            } else {
                if (r_lo < NNODES) {
                    if (c < Mout)     Y[(size_t)r_lo * Mout + c]     = acc[im][in][0];
                    if (c + 1 < Mout) Y[(size_t)r_lo * Mout + c + 1] = acc[im][in][1];
                }
                if (r_hi < NNODES) {
                    if (c < Mout)     Y[(size_t)r_hi * Mout + c]     = acc[im][in][2];
                    if (c + 1 < Mout) Y[(size_t)r_hi * Mout + c + 1] = acc[im][in][3];
                }
            }
        }
    }
}

// ---------------- aggregation: warp per node, 4-way pipelined gather ---------
// out[i] = relu?( dinv_i*(sum_e dinv_src*Y[src] + dinv_i*Y[i]) + bias )
__global__ void k_agg(const float* __restrict__ Y, const float* __restrict__ bias,
                      float* __restrict__ Hout, int Mout, int dorelu) {
    int warp = (blockIdx.x * blockDim.x + threadIdx.x) >> 5;
    int lane = threadIdx.x & 31;
    if (warp >= NNODES) return;
    int f = lane * 4;
    if (f >= Mout) return;

    int beg = g_rowoff[warp];
    int end = g_rowoff[warp + 1];
    float dv = g_dinv[warp];

    // self loop: dinv_i * Y[i]
    float4 vself = *(const float4*)(Y + (size_t)warp * Mout + f);
    float4 s0 = make_float4(dv * vself.x, dv * vself.y, dv * vself.z, dv * vself.w);
    float4 s1 = make_float4(0.f, 0.f, 0.f, 0.f);

    int j = beg;
    for (; j + 4 <= end; j += 4) {
        int i0 = __ldg(&g_esrc[j]);
        int i1 = __ldg(&g_esrc[j + 1]);
        int i2 = __ldg(&g_esrc[j + 2]);
        int i3 = __ldg(&g_esrc[j + 3]);
        float d0 = __ldg(&g_dinv[i0]);
        float d1 = __ldg(&g_dinv[i1]);
        float d2 = __ldg(&g_dinv[i2]);
        float d3 = __ldg(&g_dinv[i3]);
        float4 v0 = __ldg((const float4*)(Y + (size_t)i0 * Mout + f));
        float4 v1 = __ldg((const float4*)(Y + (size_t)i1 * Mout + f));
        float4 v2 = __ldg((const float4*)(Y + (size_t)i2 * Mout + f));
        float4 v3 = __ldg((const float4*)(Y + (size_t)i3 * Mout + f));
        s0.x = fmaf(d0, v0.x, s0.x); s0.y = fmaf(d0, v0.y, s0.y);
        s0.z = fmaf(d0, v0.z, s0.z); s0.w = fmaf(d0, v0.w, s0.w);
        s1.x = fmaf(d1, v1.x, s1.x); s1.y = fmaf(d1, v1.y, s1.y);
        s1.z = fmaf(d1, v1.z, s1.z); s1.w = fmaf(d1, v1.w, s1.w);
        s0.x = fmaf(d2, v2.x, s0.x); s0.y = fmaf(d2, v2.y, s0.y);
        s0.z = fmaf(d2, v2.z, s0.z); s0.w = fmaf(d2, v2.w, s0.w);
        s1.x = fmaf(d3, v3.x, s1.x); s1.y = fmaf(d3, v3.y, s1.y);
        s1.z = fmaf(d3, v3.z, s1.z); s1.w = fmaf(d3, v3.w, s1.w);
    }
    for (; j < end; j++) {
        int si = __ldg(&g_esrc[j]);
        float ds = __ldg(&g_dinv[si]);
        float4 v = __ldg((const float4*)(Y + (size_t)si * Mout + f));
        s0.x = fmaf(ds, v.x, s0.x); s0.y = fmaf(ds, v.y, s0.y);
        s0.z = fmaf(ds, v.z, s0.z); s0.w = fmaf(ds, v.w, s0.w);
    }
    float4 s = make_float4(s0.x + s1.x, s0.y + s1.y, s0.z + s1.z, s0.w + s1.w);

    float4 bb = *(const float4*)(bias + f);
    float4 o = make_float4(fmaf(dv, s.x, bb.x), fmaf(dv, s.y, bb.y),
                           fmaf(dv, s.z, bb.z), fmaf(dv, s.w, bb.w));
    if (dorelu) {
        o.x = fmaxf(o.x, 0.f); o.y = fmaxf(o.y, 0.f);
        o.z = fmaxf(o.z, 0.f); o.w = fmaxf(o.w, 0.f);
    }
    *(float4*)(Hout + (size_t)warp * Mout + f) = o;
}

// ---------------- launch -----------------------------------------------------
extern "C" void kernel_launch(void* const* d_in, const int* in_sizes, int n_in,
                              void* d_out, int out_size) {
    const float* x = (const float*)d_in[0];
    const int* ei = (const int*)d_in[1];
    const int* src = ei;
    const int* dst = ei + NEDGES;
    const float* W0 = (const float*)d_in[2];
    const float* b0 = (const float*)d_in[3];
    const float* W1 = (const float*)d_in[4];
    const float* b1 = (const float*)d_in[5];
    const float* W2 = (const float*)d_in[6];
    const float* b2 = (const float*)d_in[7];
    const float* W3 = (const float*)d_in[8];
    const float* b3 = (const float*)d_in[9];
    float* out = (float*)d_out;

    float *bufA, *bufB, *bufY;
    uint32_t* Wp;
    cudaGetSymbolAddress((void**)&bufA, g_bufA);
    cudaGetSymbolAddress((void**)&bufB, g_bufB);
    cudaGetSymbolAddress((void**)&bufY, g_bufY);
    cudaGetSymbolAddress((void**)&Wp, g_Wp);

    const int NT = 256;
    int gN = (NNODES + NT - 1) / NT;
    int gE = (NEDGES + NT - 1) / NT;
    int gScan = (NNODES + 1023) / 1024;

    size_t shmem = 16384 * sizeof(float);  // 64KB (As only)
    static int smem_set = 0;
    if (!smem_set) {
        cudaFuncSetAttribute(k_gemm_tc, cudaFuncAttributeMaxDynamicSharedMemorySize,
                             (int)shmem);
        smem_set = 1;
    }

    // side stream + events, created once on the first (uncaptured) call
    static cudaStream_t s_side = nullptr;
    static cudaEvent_t ev_fork = nullptr, ev_join = nullptr;
    if (s_side == nullptr) {
        cudaStreamCreateWithFlags(&s_side, cudaStreamNonBlocking);
        cudaEventCreateWithFlags(&ev_fork, cudaEventDisableTiming);
        cudaEventCreateWithFlags(&ev_join, cudaEventDisableTiming);
    }

    int gGemm = (NNODES + 127) / 128;          // 782
    int gAgg = (NNODES * 32 + NT - 1) / NT;    // 12500

    // fork: CSR build on side stream, overlapped with prepW + layer-0 GEMM
    cudaEventRecord(ev_fork, 0);
    cudaStreamWaitEvent(s_side, ev_fork, 0);
    k_init_cnt<<<gN, NT, 0, s_side>>>();
    k_count<<<gE, NT, 0, s_side>>>(dst);
    k_scan1<<<gScan, NT, 0, s_side>>>();
    k_scan2<<<1, 128, 0, s_side>>>(gScan);
    k_finalize<<<gN, NT, 0, s_side>>>();
    k_fill<<<gE, NT, 0, s_side>>>(src, dst);
    cudaEventRecord(ev_join, s_side);

    // main stream: weight prep + layer-0 GEMM (independent of CSR)
    k_prepW_all<<<256, 256>>>(W0, W1, W2, W3);
    k_gemm_tc<<<gGemm, NT, shmem>>>(x, bufY, 128, Wp);

    // join: aggregation needs CSR + dinv
    cudaStreamWaitEvent(0, ev_join, 0);
    k_agg<<<gAgg, NT>>>(bufY, b0, bufA, 128, 1);
    // layer 1
    k_gemm_tc<<<gGemm, NT, shmem>>>(bufA, bufY, 128, Wp + WPSZ);
    k_agg<<<gAgg, NT>>>(bufY, b1, bufB, 128, 1);
    // layer 2
    k_gemm_tc<<<gGemm, NT, shmem>>>(bufB, bufY, 128, Wp + 2 * WPSZ);
    k_agg<<<gAgg, NT>>>(bufY, b2, bufA, 128, 1);
    // layer 3 (C = 40, no relu)
    k_gemm_tc<<<gGemm, NT, shmem>>>(bufA, bufY, 40, Wp + 3 * WPSZ);
    k_agg<<<gAgg, NT>>>(bufY, b3, out, 40, 0);
}

// round 10
// speedup vs baseline: 1.0096x; 1.0082x over previous
#include <cuda_runtime.h>
#include <cuda_bf16.h>
#include <cstdint>
#include <cstddef>

#define NNODES 100000
#define NEDGES 500000
#define FEAT   128
#define WPSZ   16384   // uint32 per layer fragment buffer (64KB)

// ---------------- scratch (device globals; no allocations allowed) ----------
__device__ int      g_cnt[NNODES];
__device__ int      g_rowoff[NNODES + 1];
__device__ int      g_cursor[NNODES];
__device__ float    g_dinv[NNODES];
__device__ int      g_esrc[NEDGES];
__device__ float    g_bufA[(size_t)NNODES * FEAT];
__device__ float    g_bufB[(size_t)NNODES * FEAT];
__device__ float    g_bufY[(size_t)NNODES * FEAT];
__device__ uint32_t g_Wp[4 * WPSZ];   // permuted tf32 W fragments, 4 x 64KB
__device__ int      g_bsum[128];
__device__ int      g_boff[128];

// ---------------- CSR build --------------------------------------------------
__global__ void k_init_cnt() {
    int i = blockIdx.x * blockDim.x + threadIdx.x;
    if (i < NNODES) g_cnt[i] = 0;
}

__global__ void k_count(const int* __restrict__ dst) {
    int e = blockIdx.x * blockDim.x + threadIdx.x;
    if (e < NEDGES) atomicAdd(&g_cnt[dst[e]], 1);
}

__global__ void k_scan1() {
    __shared__ int sh[256];
    int t = threadIdx.x;
    int base = blockIdx.x * 1024;
    int v[4];
    int s = 0;
#pragma unroll
    for (int j = 0; j < 4; j++) {
        int idx = base + t * 4 + j;
        v[j] = (idx < NNODES) ? g_cnt[idx] : 0;
        s += v[j];
    }
    sh[t] = s;
    __syncthreads();
    for (int off = 1; off < 256; off <<= 1) {
        int x = (t >= off) ? sh[t - off] : 0;
        __syncthreads();
        sh[t] += x;
        __syncthreads();
    }
    int excl = sh[t] - s;
    if (t == 255) g_bsum[blockIdx.x] = sh[255];
    int run = excl;
#pragma unroll
    for (int j = 0; j < 4; j++) {
        int idx = base + t * 4 + j;
        if (idx < NNODES) g_rowoff[idx] = run;
        run += v[j];
    }
}

__global__ void k_scan2(int nb) {
    __shared__ int sh[128];
    int t = threadIdx.x;
    int v = (t < nb) ? g_bsum[t] : 0;
    sh[t] = v;
    __syncthreads();
    for (int off = 1; off < 128; off <<= 1) {
        int x = (t >= off) ? sh[t - off] : 0;
        __syncthreads();
        sh[t] += x;
        __syncthreads();
    }
    g_boff[t] = sh[t] - v;
}

__global__ void k_finalize() {
    int i = blockIdx.x * blockDim.x + threadIdx.x;
    if (i < NNODES) {
        int r = g_rowoff[i] + g_boff[i >> 10];
        g_rowoff[i] = r;
        g_cursor[i] = r;
        g_dinv[i] = rsqrtf((float)(g_cnt[i] + 1));
    }
    if (i == 0) g_rowoff[NNODES] = NEDGES;
}

__global__ void k_fill(const int* __restrict__ src, const int* __restrict__ dst) {
    int e = blockIdx.x * blockDim.x + threadIdx.x;
    if (e < NEDGES) {
        int p = atomicAdd(&g_cursor[dst[e]], 1);
        g_esrc[p] = src[e];
    }
}

// ---------------- W permute (all 4 layers at once) ---------------------------
__device__ __forceinline__ uint32_t f2tf32(float v) {
    uint32_t r;
    asm("cvt.rna.tf32.f32 %0, %1;" : "=r"(r) : "f"(v));
    return r;
}

__global__ void k_prepW_all(const float* __restrict__ W0, const float* __restrict__ W1,
                            const float* __restrict__ W2, const float* __restrict__ W3) {
    int gidx = blockIdx.x * blockDim.x + threadIdx.x;  // 0..65535
    int layer = gidx >> 14;
    int idx = gidx & (WPSZ - 1);
    const float* W = (layer == 0) ? W0 : (layer == 1) ? W1 : (layer == 2) ? W2 : W3;
    int Mout = (layer == 3) ? 40 : 128;
    int k = idx >> 7, c = idx & 127;
    float v = (c < Mout) ? W[k * Mout + c] : 0.f;
    int ntile = c >> 3, gid = c & 7;
    int kstep = k >> 3, klow = k & 7, slot = klow >> 2, tig = klow & 3;
    g_Wp[layer * WPSZ + ((ntile * 16 + kstep) * 32 + gid * 4 + tig) * 2 + slot] = f2tf32(v);
}

// ---------------- tensor-core GEMM ------------------------------------------
// Y[i][c] = sum_k X[i][k] * W[k][c]   (NO dinv scaling here — moved to agg)
__global__ __launch_bounds__(256, 2) void k_gemm_tc(const float* __restrict__ X,
                                                    float* __restrict__ Y, int Mout,
                                                    const uint32_t* __restrict__ Wp) {
    extern __shared__ float smem[];
    float* As = smem;  // [8 mtile][16 kstep][32 lane][4] = 16384 floats = 64KB

    int t = threadIdx.x;
    int row0 = blockIdx.x * 128;

    // X tile -> As (permuted, tf32, zero-fill OOB rows)
    for (int idx = t; idx < 128 * 32; idx += 256) {
        int r = idx >> 5;
        int kc = (idx & 31) * 4;
        int grow = row0 + r;
        float4 v = (grow < NNODES)
                       ? *(const float4*)(X + (size_t)grow * 128 + kc)
                       : make_float4(0.f, 0.f, 0.f, 0.f);
        float vv[4] = {v.x, v.y, v.z, v.w};
        int mtile = r >> 4, rlow = r & 15;
        int half = rlow >> 3, gid = rlow & 7;
#pragma unroll
        for (int j = 0; j < 4; j++) {
            int k = kc + j;
            int kstep = k >> 3, klow = k & 7, khalf = klow >> 2, tig = klow & 3;
            As[((mtile * 16 + kstep) * 32 + gid * 4 + tig) * 4 + half + 2 * khalf] =
                __uint_as_float(f2tf32(vv[j]));
        }
    }
    __syncthreads();

    int warp = t >> 5, lane = t & 31;
    int wm = warp >> 1, wn = warp & 1;  // 4 x 2 warp grid

    float acc[2][8][4];
#pragma unroll
    for (int im = 0; im < 2; im++)
#pragma unroll
        for (int in = 0; in < 8; in++)
#pragma unroll
            for (int j = 0; j < 4; j++) acc[im][in][j] = 0.f;

#pragma unroll 4
    for (int ks = 0; ks < 16; ks++) {
        uint4 a[2];
#pragma unroll
        for (int im = 0; im < 2; im++)
            a[im] = *(const uint4*)&As[(((wm * 2 + im) * 16 + ks) * 32 + lane) * 4];
        uint2 b[8];
#pragma unroll
        for (int in = 0; in < 8; in++)
            b[in] = __ldg((const uint2*)&Wp[(((wn * 8 + in) * 16 + ks) * 32 + lane) * 2]);
#pragma unroll
        for (int im = 0; im < 2; im++)
#pragma unroll
            for (int in = 0; in < 8; in++)
                asm volatile(
                    "mma.sync.aligned.m16n8k8.row.col.f32.tf32.tf32.f32 "
                    "{%0,%1,%2,%3}, {%4,%5,%6,%7}, {%8,%9}, {%0,%1,%2,%3};"
                    : "+f"(acc[im][in][0]), "+f"(acc[im][in][1]),
                      "+f"(acc[im][in][2]), "+f"(acc[im][in][3])
                    : "r"(a[im].x), "r"(a[im].y), "r"(a[im].z), "r"(a[im].w),
                      "r"(b[in].x), "r"(b[in].y));
    }

    // epilogue (no dinv)
    int gid = lane >> 2, tig = lane & 3;
#pragma unroll
    for (int im = 0; im < 2; im++) {
        int r_lo = row0 + wm * 32 + im * 16 + gid;
        int r_hi = r_lo + 8;
#pragma unroll
        for (int in = 0; in < 8; in++) {
            int c = wn * 64 + in * 8 + tig * 2;
            if (Mout == 128) {
                if (r_lo < NNODES)
                    *(float2*)(Y + (size_t)r_lo * 128 + c) =
                        make_float2(acc[im][in][0], acc[im][in][1]);
                if (r_hi < NNODES)
                    *(float2*)(Y + (size_t)r_hi * 128 + c) =
                        make_float2(acc[im][in][2], acc[im][in][3]);
            } else {
                if (r_lo < NNODES) {
                    if (c < Mout)     Y[(size_t)r_lo * Mout + c]     = acc[im][in][0];
                    if (c + 1 < Mout) Y[(size_t)r_lo * Mout + c + 1] = acc[im][in][1];
                }
                if (r_hi < NNODES) {
                    if (c < Mout)     Y[(size_t)r_hi * Mout + c]     = acc[im][in][2];
                    if (c + 1 < Mout) Y[(size_t)r_hi * Mout + c + 1] = acc[im][in][3];
                }
            }
        }
    }
}

// ---------------- aggregation: warp per node, 4-way pipelined gather ---------
// out[i] = relu?( dinv_i*(sum_e dinv_src*Y[src] + dinv_i*Y[i]) + bias )
__global__ void k_agg(const float* __restrict__ Y, const float* __restrict__ bias,
                      float* __restrict__ Hout, int Mout, int dorelu) {
    int warp = (blockIdx.x * blockDim.x + threadIdx.x) >> 5;
    int lane = threadIdx.x & 31;
    if (warp >= NNODES) return;
    int f = lane * 4;
    if (f >= Mout) return;

    int beg = g_rowoff[warp];
    int end = g_rowoff[warp + 1];
    float dv = g_dinv[warp];

    // self loop: dinv_i * Y[i]
    float4 vself = *(const float4*)(Y + (size_t)warp * Mout + f);
    float4 s0 = make_float4(dv * vself.x, dv * vself.y, dv * vself.z, dv * vself.w);
    float4 s1 = make_float4(0.f, 0.f, 0.f, 0.f);

    int j = beg;
    for (; j + 4 <= end; j += 4) {
        int i0 = __ldg(&g_esrc[j]);
        int i1 = __ldg(&g_esrc[j + 1]);
        int i2 = __ldg(&g_esrc[j + 2]);
        int i3 = __ldg(&g_esrc[j + 3]);
        float d0 = __ldg(&g_dinv[i0]);
        float d1 = __ldg(&g_dinv[i1]);
        float d2 = __ldg(&g_dinv[i2]);
        float d3 = __ldg(&g_dinv[i3]);
        float4 v0 = __ldg((const float4*)(Y + (size_t)i0 * Mout + f));
        float4 v1 = __ldg((const float4*)(Y + (size_t)i1 * Mout + f));
        float4 v2 = __ldg((const float4*)(Y + (size_t)i2 * Mout + f));
        float4 v3 = __ldg((const float4*)(Y + (size_t)i3 * Mout + f));
        s0.x = fmaf(d0, v0.x, s0.x); s0.y = fmaf(d0, v0.y, s0.y);
        s0.z = fmaf(d0, v0.z, s0.z); s0.w = fmaf(d0, v0.w, s0.w);
        s1.x = fmaf(d1, v1.x, s1.x); s1.y = fmaf(d1, v1.y, s1.y);
        s1.z = fmaf(d1, v1.z, s1.z); s1.w = fmaf(d1, v1.w, s1.w);
        s0.x = fmaf(d2, v2.x, s0.x); s0.y = fmaf(d2, v2.y, s0.y);
        s0.z = fmaf(d2, v2.z, s0.z); s0.w = fmaf(d2, v2.w, s0.w);
        s1.x = fmaf(d3, v3.x, s1.x); s1.y = fmaf(d3, v3.y, s1.y);
        s1.z = fmaf(d3, v3.z, s1.z); s1.w = fmaf(d3, v3.w, s1.w);
    }
    for (; j < end; j++) {
        int si = __ldg(&g_esrc[j]);
        float ds = __ldg(&g_dinv[si]);
        float4 v = __ldg((const float4*)(Y + (size_t)si * Mout + f));
        s0.x = fmaf(ds, v.x, s0.x); s0.y = fmaf(ds, v.y, s0.y);
        s0.z = fmaf(ds, v.z, s0.z); s0.w = fmaf(ds, v.w, s0.w);
    }
    float4 s = make_float4(s0.x + s1.x, s0.y + s1.y, s0.z + s1.z, s0.w + s1.w);

    float4 bb = *(const float4*)(bias + f);
    float4 o = make_float4(fmaf(dv, s.x, bb.x), fmaf(dv, s.y, bb.y),
                           fmaf(dv, s.z, bb.z), fmaf(dv, s.w, bb.w));
    if (dorelu) {
        o.x = fmaxf(o.x, 0.f); o.y = fmaxf(o.y, 0.f);
        o.z = fmaxf(o.z, 0.f); o.w = fmaxf(o.w, 0.f);
    }
    *(float4*)(Hout + (size_t)warp * Mout + f) = o;
}

// ---------------- launch -----------------------------------------------------
extern "C" void kernel_launch(void* const* d_in, const int* in_sizes, int n_in,
                              void* d_out, int out_size) {
    const float* x = (const float*)d_in[0];
    const int* ei = (const int*)d_in[1];
    const int* src = ei;
    const int* dst = ei + NEDGES;
    const float* W0 = (const float*)d_in[2];
    const float* b0 = (const float*)d_in[3];
    const float* W1 = (const float*)d_in[4];
    const float* b1 = (const float*)d_in[5];
    const float* W2 = (const float*)d_in[6];
    const float* b2 = (const float*)d_in[7];
    const float* W3 = (const float*)d_in[8];
    const float* b3 = (const float*)d_in[9];
    float* out = (float*)d_out;

    float *bufA, *bufB, *bufY;
    uint32_t* Wp;
    cudaGetSymbolAddress((void**)&bufA, g_bufA);
    cudaGetSymbolAddress((void**)&bufB, g_bufB);
    cudaGetSymbolAddress((void**)&bufY, g_bufY);
    cudaGetSymbolAddress((void**)&Wp, g_Wp);

    const int NT = 256;
    int gN = (NNODES + NT - 1) / NT;
    int gE = (NEDGES + NT - 1) / NT;
    int gScan = (NNODES + 1023) / 1024;

    size_t shmem = 16384 * sizeof(float);  // 64KB (As only)
    static int smem_set = 0;
    if (!smem_set) {
        cudaFuncSetAttribute(k_gemm_tc, cudaFuncAttributeMaxDynamicSharedMemorySize,
                             (int)shmem);
        smem_set = 1;
    }

    // side stream + events, created once on the first (uncaptured) call
    static cudaStream_t s_side = nullptr;
    static cudaEvent_t ev_fork = nullptr, ev_join = nullptr;
    if (s_side == nullptr) {
        cudaStreamCreateWithFlags(&s_side, cudaStreamNonBlocking);
        cudaEventCreateWithFlags(&ev_fork, cudaEventDisableTiming);
        cudaEventCreateWithFlags(&ev_join, cudaEventDisableTiming);
    }

    int gGemm = (NNODES + 127) / 128;          // 782
    int gAgg = (NNODES * 32 + NT - 1) / NT;    // 12500

    // fork: CSR build on side stream, overlapped with prepW + layer-0 GEMM
    cudaEventRecord(ev_fork, 0);
    cudaStreamWaitEvent(s_side, ev_fork, 0);
    k_init_cnt<<<gN, NT, 0, s_side>>>();
    k_count<<<gE, NT, 0, s_side>>>(dst);
    k_scan1<<<gScan, NT, 0, s_side>>>();
    k_scan2<<<1, 128, 0, s_side>>>(gScan);
    k_finalize<<<gN, NT, 0, s_side>>>();
    k_fill<<<gE, NT, 0, s_side>>>(src, dst);
    cudaEventRecord(ev_join, s_side);

    // main stream: weight prep + layer-0 GEMM (independent of CSR)
    k_prepW_all<<<256, 256>>>(W0, W1, W2, W3);
    k_gemm_tc<<<gGemm, NT, shmem>>>(x, bufY, 128, Wp);

    // join: aggregation needs CSR + dinv
    cudaStreamWaitEvent(0, ev_join, 0);
    k_agg<<<gAgg, NT>>>(bufY, b0, bufA, 128, 1);
    // layer 1
    k_gemm_tc<<<gGemm, NT, shmem>>>(bufA, bufY, 128, Wp + WPSZ);
    k_agg<<<gAgg, NT>>>(bufY, b1, bufB, 128, 1);
    // layer 2
    k_gemm_tc<<<gGemm, NT, shmem>>>(bufB, bufY, 128, Wp + 2 * WPSZ);
    k_agg<<<gAgg, NT>>>(bufY, b2, bufA, 128, 1);
    // layer 3 (C = 40, no relu)
    k_gemm_tc<<<gGemm, NT, shmem>>>(bufA, bufY, 40, Wp + 3 * WPSZ);
    k_agg<<<gAgg, NT>>>(bufY, b3, out, 40, 0);
}